// round 1
// baseline (speedup 1.0000x reference)
#include <cuda_runtime.h>
#include <math.h>

// ContinuousConv1d: out[b,t2,o] = sum_{c,m} kernel[o,c,m] * xs[b,t2,c,m] + bias[o]
// xs[m,c] = sum_k w(f)[(k-m) mod 64] * xwin[k,c]  (fractional-delay Dirichlet filter)

#define NB   4
#define NT1  4096
#define NT2  512
#define NIC  32
#define NOC  64
#define NKS  64
#define NPOS (NB*NT2)     // 2048
#define PP   16           // positions per CTA
#define NCTA (NPOS/PP)    // 128
#define NTHR 256
#define CMTOT 2048        // IC*KS flattened (c*64+m, matches kernel[o][c][m])
#define CHK  64           // cm chunk staged per GEMM step
#define KTP  68           // kt smem pitch (floats): conflict-free LDS.128 per 8-lane wavefront

__global__ __launch_bounds__(NTHR, 1)
void cc1d_fused(const float* __restrict__ x, const float* __restrict__ idxg,
                const float* __restrict__ kern, const float* __restrict__ bias,
                float* __restrict__ out)
{
    extern __shared__ float sm[];
    float* xs = sm;                     // PP * 2048 floats (128 KB)
    float* xw = xs + PP*CMTOT;          // 64 x 32 window (8 KB)
    float* ws = xw + CMTOT;             // 64 Dirichlet taps
    float* kt = ws + 64;                // 64 x 68 kernel tile (17 KB)

    const int t = threadIdx.x;
    const int pos0 = blockIdx.x * PP;

    // ---------------- Phase A: build xs for PP positions ----------------
    for (int p = 0; p < PP; ++p) {
        const int pos = pos0 + p;
        const float iv = idxg[pos];
        const float fi = floorf(iv);
        const int   ii = (int)fi;
        const float f  = iv - fi;
        const int   b  = pos >> 9;      // T2 = 512

        // load centered window x_pad[ii + k], k=0..63 (zero pad outside [0,T1))
        #pragma unroll
        for (int r = 0; r < 2; ++r) {
            int s  = t + r*NTHR;        // 0..511 float4 slots
            int k  = s >> 3;            // row (8 float4 per 32-float row)
            int c4 = s & 7;
            int t1 = ii + k - (NKS/2);
            float4 v = make_float4(0.f, 0.f, 0.f, 0.f);
            if (t1 >= 0 && t1 < NT1)
                v = reinterpret_cast<const float4*>(x)[(b*NT1 + t1)*8 + c4];
            reinterpret_cast<float4*>(xw)[s] = v;
        }

        // Dirichlet taps: w[j] = (1/64)(1 + 2*S + cos(pi(f+j)))
        // S = sum_{q=1}^{31} cos(pi q (f+j)/32) = sin(31a/2) cos(16a) / sin(a/2)
        if (t < NKS) {
            float u  = f + (float)t;
            float a  = u * 0.098174770424681038f;  // pi/32
            float s2 = sinf(0.5f*a);
            float wv;
            if (fabsf(s2) < 1e-5f) wv = 1.f;       // u ~ 0 or 64: limit is 1
            else wv = (1.f + 2.f*sinf(15.5f*a)*cosf(16.f*a)/s2 + cosf(32.f*a)) * (1.f/64.f);
            ws[t] = wv;
        }
        __syncthreads();

        // xs[c][m] = sum_k w[(k-m)&63] * xw[k][c]; thread = (m = t&63, cg = t>>6)
        const int m  = t & 63;
        const int cg = t >> 6;          // 0..3, covers c = cg*8 .. cg*8+7
        float acc[8];
        #pragma unroll
        for (int i = 0; i < 8; ++i) acc[i] = 0.f;
        const float4* xw4 = reinterpret_cast<const float4*>(xw);
        #pragma unroll 8
        for (int k = 0; k < NKS; ++k) {
            float  wv = ws[(k - m) & 63];          // conflict-free (distinct mod 32)
            float4 a4 = xw4[k*8 + cg*2];           // warp-uniform broadcast
            float4 b4 = xw4[k*8 + cg*2 + 1];
            acc[0] += wv*a4.x; acc[1] += wv*a4.y; acc[2] += wv*a4.z; acc[3] += wv*a4.w;
            acc[4] += wv*b4.x; acc[5] += wv*b4.y; acc[6] += wv*b4.z; acc[7] += wv*b4.w;
        }
        float* xsp = xs + p*CMTOT;
        #pragma unroll
        for (int i = 0; i < 8; ++i)
            xsp[(cg*8 + i)*64 + m] = acc[i];       // consecutive m -> conflict-free STS
        __syncthreads();
    }

    // ---------------- Phase B: out[p][o] = kernel[o][:] . xs[p][:] ----------------
    const int o  = t & 63;
    const int ph = t >> 6;              // p = ph*4 + i, i=0..3
    float acc[4] = {0.f, 0.f, 0.f, 0.f};
    const float4* x0 = reinterpret_cast<const float4*>(xs + (ph*4 + 0)*CMTOT);
    const float4* x1 = reinterpret_cast<const float4*>(xs + (ph*4 + 1)*CMTOT);
    const float4* x2 = reinterpret_cast<const float4*>(xs + (ph*4 + 2)*CMTOT);
    const float4* x3 = reinterpret_cast<const float4*>(xs + (ph*4 + 3)*CMTOT);
    const float* ktro = kt + o*KTP;

    for (int chunk = 0; chunk < CMTOT/CHK; ++chunk) {
        __syncthreads();                // previous chunk fully consumed
        // stage kernel tile: kt[oo][j] = kern[oo*2048 + chunk*64 + j]
        #pragma unroll
        for (int r = 0; r < 4; ++r) {
            int v  = t + r*NTHR;        // 0..1023 float4 slots
            int oo = v >> 4;
            int j4 = v & 15;
            float4 kv = reinterpret_cast<const float4*>(kern + oo*CMTOT + chunk*CHK)[j4];
            *reinterpret_cast<float4*>(kt + oo*KTP + j4*4) = kv;
        }
        __syncthreads();

        const int base = chunk*16;      // float4 index into xs rows
        #pragma unroll
        for (int jq = 0; jq < 16; ++jq) {
            float4 kq = *reinterpret_cast<const float4*>(ktro + jq*4);
            float4 q0 = x0[base + jq];
            float4 q1 = x1[base + jq];
            float4 q2 = x2[base + jq];
            float4 q3 = x3[base + jq];
            acc[0] += kq.x*q0.x + kq.y*q0.y + kq.z*q0.z + kq.w*q0.w;
            acc[1] += kq.x*q1.x + kq.y*q1.y + kq.z*q1.z + kq.w*q1.w;
            acc[2] += kq.x*q2.x + kq.y*q2.y + kq.z*q2.z + kq.w*q2.w;
            acc[3] += kq.x*q3.x + kq.y*q3.y + kq.z*q3.z + kq.w*q3.w;
        }
    }

    const float bv = bias[o];
    #pragma unroll
    for (int i = 0; i < 4; ++i)
        out[(pos0 + ph*4 + i)*NOC + o] = acc[i] + bv;
}

extern "C" void kernel_launch(void* const* d_in, const int* in_sizes, int n_in,
                              void* d_out, int out_size)
{
    const float* x    = (const float*)d_in[0];
    const float* idx  = (const float*)d_in[1];
    const float* kern = (const float*)d_in[2];
    const float* bias = (const float*)d_in[3];
    float* out = (float*)d_out;
    (void)in_sizes; (void)n_in; (void)out_size;

    const size_t smem = (size_t)(PP*CMTOT + CMTOT + 64 + 64*KTP) * sizeof(float); // ~153 KB
    cudaFuncSetAttribute(cc1d_fused, cudaFuncAttributeMaxDynamicSharedMemorySize, (int)smem);
    cc1d_fused<<<NCTA, NTHR, smem>>>(x, idx, kern, bias, out);
}

// round 2
// speedup vs baseline: 1.4356x; 1.4356x over previous
#include <cuda_runtime.h>
#include <math.h>

// ContinuousConv1d via Dirichlet circulant + GEMM, fp32x2 packed math.
// out[b,t2,o] = sum_{c,m} kernel[o,c,m] * xs[b,t2,c,m] + bias[o]
// xs[c,m] = sum_k w_f[(k-m) mod 64] * xwin[k,c]

#define NB   4
#define NT1  4096
#define NT2  512
#define NIC  32
#define NOC  64
#define NKS  64
#define NPOS (NB*NT2)     // 2048
#define PP   16           // positions per CTA
#define NCTA (NPOS/PP)    // 128
#define NTHR 512
#define CMTOT 2048        // ic*ks flattened, j = c*64 + m
#define XSP  2052         // xs row pitch (floats): 4 mod 32 -> conflict-free

// smem layout (floats)
#define OFF_XS 0
#define OFF_XW (PP*XSP)              // 32832 : 4 x 2048 window (k-major)
#define OFF_WS (OFF_XW + 4*2048)     // 41024 : 4 x 64 taps
#define OFF_KT (OFF_WS + 4*64)       // 41280 : 2 x 4096 kernel tile (double buf)
#define SM_FLOATS (OFF_KT + 2*4096)  // 49472 floats = 197888 B

__device__ __forceinline__ unsigned long long packdup(float v) {
    unsigned long long r;
    asm("mov.b64 %0, {%1, %1};" : "=l"(r) : "f"(v));
    return r;
}
__device__ __forceinline__ void ffma2(unsigned long long& c,
                                      unsigned long long a, unsigned long long b) {
    asm("fma.rn.f32x2 %0, %1, %2, %0;" : "+l"(c) : "l"(a), "l"(b));
}
__device__ __forceinline__ float2 u2f2(unsigned long long v) {
    float2 r;
    asm("mov.b64 {%0, %1}, %2;" : "=f"(r.x), "=f"(r.y) : "l"(v));
    return r;
}

__global__ __launch_bounds__(NTHR, 1)
void cc1d_fused2(const float* __restrict__ x, const float* __restrict__ idxg,
                 const float* __restrict__ kern, const float* __restrict__ bias,
                 float* __restrict__ out)
{
    extern __shared__ float sm[];
    float* xs = sm + OFF_XS;
    float* xw = sm + OFF_XW;
    float* ws = sm + OFF_WS;
    float* kt = sm + OFF_KT;

    const int t = threadIdx.x;
    const int pos0 = blockIdx.x * PP;

    // ================= Phase A: build xs (4 positions per step) =================
    const int subA = t >> 7;            // 0..3 position within group
    const int ttA  = t & 127;
    const int m0   = ttA & 31;          // thread handles m0 and m0+32
    const int cgA  = ttA >> 5;          // 0..3 -> c base = cgA*8

    float4 wreg[4];
    int pstep;

    // prefetch window for pstep into wreg
    #define LOAD_WINDOW(PS) do {                                               \
        int p_  = (PS)*4 + subA;                                               \
        int gp_ = pos0 + p_;                                                   \
        float iv_ = idxg[gp_];                                                 \
        int ii_ = (int)floorf(iv_);                                            \
        int b_  = gp_ >> 9;                                                    \
        _Pragma("unroll")                                                      \
        for (int r_ = 0; r_ < 4; ++r_) {                                       \
            int s_  = ttA + r_*128;     /* 0..511 float4 slots */              \
            int k_  = s_ >> 3;                                                 \
            int c4_ = s_ & 7;                                                  \
            int t1_ = ii_ + k_ - (NKS/2);                                      \
            float4 v_ = make_float4(0.f,0.f,0.f,0.f);                          \
            if (t1_ >= 0 && t1_ < NT1)                                         \
                v_ = reinterpret_cast<const float4*>(x)[(b_*NT1 + t1_)*8 + c4_];\
            wreg[r_] = v_;                                                     \
        }                                                                      \
    } while (0)

    LOAD_WINDOW(0);

    for (pstep = 0; pstep < 4; ++pstep) {
        __syncthreads();   // previous compute done reading xw/ws
        // stage window
        #pragma unroll
        for (int r = 0; r < 4; ++r) {
            int s = ttA + r*128;
            reinterpret_cast<float4*>(xw + subA*2048)[s] = wreg[r];
        }
        // taps for the 4 positions of this step (256 threads)
        if (t < 256) {
            int sub2 = t >> 6;
            int j    = t & 63;
            float iv = idxg[pos0 + pstep*4 + sub2];
            float f  = iv - floorf(iv);
            float u  = f + (float)j;
            float a  = u * 0.098174770424681038f;   // pi/32
            float s2 = sinf(0.5f*a);
            float wv;
            if (fabsf(s2) < 1e-5f) wv = 1.f;
            else wv = (1.f + 2.f*sinf(15.5f*a)*cosf(16.f*a)/s2 + cosf(32.f*a)) * (1.f/64.f);
            ws[sub2*64 + j] = wv;
        }
        __syncthreads();   // xw, ws visible

        if (pstep < 3) LOAD_WINDOW(pstep + 1);   // hide global latency behind compute

        // circulant: acc[h][q] pairs over (c,c+1), h = m-half
        unsigned long long acc[2][4];
        #pragma unroll
        for (int h = 0; h < 2; ++h)
            #pragma unroll
            for (int q = 0; q < 4; ++q) acc[h][q] = 0ull;

        const float* wsub = ws + subA*64;
        const float* xwb  = xw + subA*2048 + cgA*8;
        #pragma unroll 4
        for (int k = 0; k < NKS; ++k) {
            float wa = wsub[(k - m0) & 63];
            float wb = wsub[(k - m0 - 32) & 63];
            unsigned long long wa2 = packdup(wa);
            unsigned long long wb2 = packdup(wb);
            ulonglong2 xA = *reinterpret_cast<const ulonglong2*>(xwb + k*32);
            ulonglong2 xB = *reinterpret_cast<const ulonglong2*>(xwb + k*32 + 4);
            ffma2(acc[0][0], wa2, xA.x); ffma2(acc[0][1], wa2, xA.y);
            ffma2(acc[0][2], wa2, xB.x); ffma2(acc[0][3], wa2, xB.y);
            ffma2(acc[1][0], wb2, xA.x); ffma2(acc[1][1], wb2, xA.y);
            ffma2(acc[1][2], wb2, xB.x); ffma2(acc[1][3], wb2, xB.y);
        }
        // store xs: pair q covers channels (cgA*8+2q, cgA*8+2q+1)
        float* xsp = xs + (pstep*4 + subA)*XSP;
        #pragma unroll
        for (int h = 0; h < 2; ++h) {
            int m = m0 + h*32;
            #pragma unroll
            for (int q = 0; q < 4; ++q) {
                float2 v = u2f2(acc[h][q]);
                xsp[(cgA*8 + 2*q    )*64 + m] = v.x;
                xsp[(cgA*8 + 2*q + 1)*64 + m] = v.y;
            }
        }
    }

    // ================= Phase B: out = xs @ kern^T + bias =================
    // thread: pg = t&3 (p = i*4+pg), og = (t>>2)&15 (o = og*4+ii), g = t>>6 (j-split 8-way)
    const int pg  = t & 3;
    const int og  = (t >> 2) & 15;
    const int g   = t >> 6;
    const int key = og & 3;              // kt xor-swizzle key

    float4 kreg[2];
    #define LOAD_KT(CH) do {                                                   \
        _Pragma("unroll")                                                      \
        for (int r_ = 0; r_ < 2; ++r_) {                                       \
            int v_  = t + r_*512;        /* 0..1023 = 64 o x 16 jblk */        \
            int oo_ = v_ >> 4;                                                 \
            int jb_ = v_ & 15;                                                 \
            kreg[r_] = reinterpret_cast<const float4*>(kern)[oo_*512 + (CH)*16 + jb_]; \
        }                                                                      \
    } while (0)

    LOAD_KT(0);

    unsigned long long acc[4][4];        // [ii][i], pairs over (j_even, j_odd)
    #pragma unroll
    for (int a = 0; a < 4; ++a)
        #pragma unroll
        for (int b = 0; b < 4; ++b) acc[a][b] = 0ull;

    for (int chunk = 0; chunk < CMTOT/64; ++chunk) {
        const int buf = chunk & 1;
        float* ktb = kt + buf*4096;
        // stage kernel tile with xor swizzle on float4 slot
        #pragma unroll
        for (int r = 0; r < 2; ++r) {
            int v  = t + r*512;
            int oo = v >> 4;
            int jb = v & 15;
            int slot = jb ^ ((oo >> 2) & 3);
            *reinterpret_cast<float4*>(ktb + oo*64 + slot*4) = kreg[r];
        }
        __syncthreads();
        if (chunk < CMTOT/64 - 1) LOAD_KT(chunk + 1);

        #pragma unroll
        for (int qq = 0; qq < 2; ++qq) {
            const int j4 = g*2 + qq;                 // float4 slot in chunk
            const int slot = j4 ^ key;
            ulonglong2 kk[4];
            #pragma unroll
            for (int ii = 0; ii < 4; ++ii)
                kk[ii] = *reinterpret_cast<const ulonglong2*>(ktb + (og*4 + ii)*64 + slot*4);
            ulonglong2 xx[4];
            #pragma unroll
            for (int i = 0; i < 4; ++i)
                xx[i] = *reinterpret_cast<const ulonglong2*>(xs + (i*4 + pg)*XSP + chunk*64 + j4*4);
            #pragma unroll
            for (int ii = 0; ii < 4; ++ii)
                #pragma unroll
                for (int i = 0; i < 4; ++i) {
                    ffma2(acc[ii][i], kk[ii].x, xx[i].x);
                    ffma2(acc[ii][i], kk[ii].y, xx[i].y);
                }
        }
        __syncthreads();   // reads of ktb done before next staging overwrite cycle
    }

    // ================= Reduction over the 8 j-splits =================
    // red (aliases xs region): [64 slot][8 g][16 e] of 8B pairs
    unsigned long long* red = reinterpret_cast<unsigned long long*>(sm);
    const int slotw = t & 63;            // (og<<2)|pg
    #pragma unroll
    for (int ii = 0; ii < 4; ++ii)
        #pragma unroll
        for (int i = 0; i < 4; ++i)
            red[(slotw*8 + g)*16 + ii*4 + i] = acc[ii][i];
    __syncthreads();

    #pragma unroll
    for (int h = 0; h < 2; ++h) {
        int u    = t*2 + h;              // 0..1023 outputs
        int slot = u >> 4;
        int e    = u & 15;
        float sx = 0.f, sy = 0.f;
        #pragma unroll
        for (int gg = 0; gg < 8; ++gg) {
            float2 v = u2f2(red[(slot*8 + gg)*16 + e]);
            sx += v.x; sy += v.y;
        }
        int pgg = slot & 3, ogg = slot >> 2;
        int ii = e >> 2, i = e & 3;
        int o = ogg*4 + ii;
        int p = i*4 + pgg;
        out[(pos0 + p)*NOC + o] = sx + sy + bias[o];
    }
}

extern "C" void kernel_launch(void* const* d_in, const int* in_sizes, int n_in,
                              void* d_out, int out_size)
{
    const float* x    = (const float*)d_in[0];
    const float* idx  = (const float*)d_in[1];
    const float* kern = (const float*)d_in[2];
    const float* bias = (const float*)d_in[3];
    float* out = (float*)d_out;
    (void)in_sizes; (void)n_in; (void)out_size;

    const size_t smem = (size_t)SM_FLOATS * sizeof(float);   // ~193 KB
    cudaFuncSetAttribute(cc1d_fused2, cudaFuncAttributeMaxDynamicSharedMemorySize, (int)smem);
    cc1d_fused2<<<NCTA, NTHR, smem>>>(x, idx, kern, bias, out);
}

// round 3
// speedup vs baseline: 1.7696x; 1.2326x over previous
#include <cuda_runtime.h>
#include <math.h>

// ContinuousConv1d = Dirichlet circulant (phase A) + GEMM vs kernel^T (phase B).
// xs[p, c*64+m] = sum_k w_{f(p)}[(k-m)&63] * xwin_p[k, c]
// out[p, o]    = bias[o] + sum_j kernel[o, j] * xs[p, j]

#define NB   4
#define NT1  4096
#define NT2  512
#define NIC  32
#define NOC  64
#define NKS  64
#define NPOS 2048
#define CM   2048          // ic*ks flattened, j = c*64 + m

__device__ float g_xs[NPOS * CM];   // 16 MB scratch

static __device__ __forceinline__ unsigned long long packdup(float v) {
    unsigned long long r; asm("mov.b64 %0, {%1, %1};" : "=l"(r) : "f"(v)); return r;
}
static __device__ __forceinline__ void ffma2(unsigned long long& c,
                                             unsigned long long a, unsigned long long b) {
    asm("fma.rn.f32x2 %0, %1, %2, %0;" : "+l"(c) : "l"(a), "l"(b));
}
static __device__ __forceinline__ float2 u2f2(unsigned long long v) {
    float2 r; asm("mov.b64 {%0, %1}, %2;" : "=f"(r.x), "=f"(r.y) : "l"(v)); return r;
}

// ---------------- init: out = bias ----------------
__global__ void cc1d_init(const float* __restrict__ bias, float* __restrict__ out) {
    int i = blockIdx.x * blockDim.x + threadIdx.x;     // 131072 elements
    out[i] = bias[i & 63];
}

// ---------------- Phase A: 4 positions per CTA, 256 threads ----------------
__global__ __launch_bounds__(256, 3)
void cc1d_phaseA(const float* __restrict__ x, const float* __restrict__ idxg) {
    __shared__ float xw[4 * 2048];    // 4 windows, k-major [k][c]
    __shared__ float ws[4 * 64];      // 4 tap vectors

    const int t = threadIdx.x;
    const int pos0 = blockIdx.x * 4;
    const int b = pos0 >> 9;          // all 4 positions share batch (512 % 4 == 0)

    float iv[4]; int ibase[4];
    #pragma unroll
    for (int s = 0; s < 4; ++s) { iv[s] = idxg[pos0 + s]; ibase[s] = (int)floorf(iv[s]); }

    // stage 4 windows: 2048 float4 slots
    #pragma unroll
    for (int r = 0; r < 8; ++r) {
        int s   = t + r * 256;        // 0..2047
        int sub = s >> 9;
        int s2  = s & 511;
        int k   = s2 >> 3, c4 = s2 & 7;
        int t1  = ibase[sub] + k - (NKS / 2);
        float4 v = make_float4(0.f, 0.f, 0.f, 0.f);
        if (t1 >= 0 && t1 < NT1)
            v = reinterpret_cast<const float4*>(x)[(b * NT1 + t1) * 8 + c4];
        reinterpret_cast<float4*>(xw)[s] = v;
    }
    // Dirichlet taps: w[j] = (1/64)(1 + 2*sin(15.5a)cos(16a)/sin(a/2) + cos(32a)), a = pi(f+j)/32
    {
        int sub = t >> 6, j = t & 63;
        float f  = iv[sub] - floorf(iv[sub]);
        float u  = f + (float)j;
        float a  = u * 0.098174770424681038f;  // pi/32
        float s2 = sinf(0.5f * a);
        float wv;
        if (fabsf(s2) < 1e-5f) wv = 1.f;
        else wv = (1.f + 2.f * sinf(15.5f * a) * cosf(16.f * a) / s2 + cosf(32.f * a)) * (1.f / 64.f);
        ws[sub * 64 + j] = wv;
    }
    __syncthreads();

    // circulant: thread = (sub = t>>6, m0 = t&31, cg = (t>>5)&1 -> 16 channels)
    const int sub = t >> 6;
    const int tt  = t & 63;
    const int m0  = tt & 31;
    const int cg  = tt >> 5;
    const float* wsp = ws + sub * 64;
    const float* xwp = xw + sub * 2048 + cg * 16;

    unsigned long long acc[2][8];
    #pragma unroll
    for (int h = 0; h < 2; ++h)
        #pragma unroll
        for (int q = 0; q < 8; ++q) acc[h][q] = 0ull;

    #pragma unroll 8
    for (int k = 0; k < NKS; ++k) {
        unsigned long long wa = packdup(wsp[(k - m0) & 63]);
        unsigned long long wb = packdup(wsp[(k - m0 - 32) & 63]);
        const ulonglong2* row = reinterpret_cast<const ulonglong2*>(xwp + k * 32);
        ulonglong2 xA = row[0], xB = row[1], xC = row[2], xD = row[3];   // 16 ch = 8 pairs
        ffma2(acc[0][0], wa, xA.x); ffma2(acc[0][1], wa, xA.y);
        ffma2(acc[0][2], wa, xB.x); ffma2(acc[0][3], wa, xB.y);
        ffma2(acc[0][4], wa, xC.x); ffma2(acc[0][5], wa, xC.y);
        ffma2(acc[0][6], wa, xD.x); ffma2(acc[0][7], wa, xD.y);
        ffma2(acc[1][0], wb, xA.x); ffma2(acc[1][1], wb, xA.y);
        ffma2(acc[1][2], wb, xB.x); ffma2(acc[1][3], wb, xB.y);
        ffma2(acc[1][4], wb, xC.x); ffma2(acc[1][5], wb, xC.y);
        ffma2(acc[1][6], wb, xD.x); ffma2(acc[1][7], wb, xD.y);
    }

    // store xs: pair q covers channels (cg*16+2q, +1); lanes m0 -> coalesced 128B
    float* dst = g_xs + (size_t)(pos0 + sub) * CM;
    #pragma unroll
    for (int h = 0; h < 2; ++h) {
        int m = m0 + h * 32;
        #pragma unroll
        for (int q = 0; q < 8; ++q) {
            float2 v = u2f2(acc[h][q]);
            dst[(cg * 16 + 2 * q) * 64 + m]     = v.x;
            dst[(cg * 16 + 2 * q + 1) * 64 + m] = v.y;
        }
    }
}

// ---------------- Phase B: out += xs @ kernel^T ----------------
#define MT   64            // positions per CTA
#define KSPL 16            // K-splits
#define JR   (CM / KSPL)   // 128 j per CTA
#define XTP  132           // xt pitch (floats)

__global__ __launch_bounds__(256, 3)
void cc1d_phaseB(const float* __restrict__ kern, float* __restrict__ out) {
    extern __shared__ float smB[];
    float* xt = smB;                  // MT x XTP          (33792 B)
    float* kt = smB + MT * XTP;       // NOC x JR, xor-swizzled (32768 B)

    const int t  = threadIdx.x;
    const int mt = blockIdx.x >> 4;   // 0..31
    const int ks = blockIdx.x & 15;   // 0..15
    const int p0 = mt * MT;
    const int j0 = ks * JR;

    // stage xs tile: 64 rows x 32 float4
    #pragma unroll 4
    for (int r = 0; r < 8; ++r) {
        int v = t + r * 256;
        int row = v >> 5, j4 = v & 31;
        float4 d = reinterpret_cast<const float4*>(g_xs + (size_t)(p0 + row) * CM + j0)[j4];
        *reinterpret_cast<float4*>(xt + row * XTP + j4 * 4) = d;
    }
    // stage kernel tile with xor swizzle: slot = jb ^ ((row>>2)&15)
    #pragma unroll 4
    for (int r = 0; r < 8; ++r) {
        int v = t + r * 256;
        int row = v >> 5, jb = v & 31;
        float4 d = reinterpret_cast<const float4*>(kern + (size_t)row * CM + j0)[jb];
        int slot = jb ^ ((row >> 2) & 15);
        *reinterpret_cast<float4*>(kt + row * JR + slot * 4) = d;
    }
    __syncthreads();

    const int og = t & 15;            // o = og*4 + ii
    const int pg = t >> 4;            // p = pg*4 + i
    unsigned long long acc[4][4];
    #pragma unroll
    for (int a = 0; a < 4; ++a)
        #pragma unroll
        for (int c = 0; c < 4; ++c) acc[a][c] = 0ull;

    const float* ktb = kt + og * 4 * JR;
    const float* xtb = xt + pg * 4 * XTP;

    #pragma unroll 4
    for (int qq = 0; qq < 32; ++qq) {
        const int slot = qq ^ og;     // key(row) = row>>2 = og for all 4 ii
        ulonglong2 kk[4];
        #pragma unroll
        for (int ii = 0; ii < 4; ++ii)
            kk[ii] = *reinterpret_cast<const ulonglong2*>(ktb + ii * JR + slot * 4);
        ulonglong2 xx[4];
        #pragma unroll
        for (int i = 0; i < 4; ++i)
            xx[i] = *reinterpret_cast<const ulonglong2*>(xtb + i * XTP + qq * 4);
        #pragma unroll
        for (int ii = 0; ii < 4; ++ii)
            #pragma unroll
            for (int i = 0; i < 4; ++i) {
                ffma2(acc[ii][i], kk[ii].x, xx[i].x);
                ffma2(acc[ii][i], kk[ii].y, xx[i].y);
            }
    }

    // epilogue: accumulate K-split partials
    #pragma unroll
    for (int ii = 0; ii < 4; ++ii)
        #pragma unroll
        for (int i = 0; i < 4; ++i) {
            float2 v = u2f2(acc[ii][i]);
            atomicAdd(&out[(size_t)(p0 + pg * 4 + i) * NOC + og * 4 + ii], v.x + v.y);
        }
}

extern "C" void kernel_launch(void* const* d_in, const int* in_sizes, int n_in,
                              void* d_out, int out_size)
{
    const float* x    = (const float*)d_in[0];
    const float* idx  = (const float*)d_in[1];
    const float* kern = (const float*)d_in[2];
    const float* bias = (const float*)d_in[3];
    float* out = (float*)d_out;
    (void)in_sizes; (void)n_in; (void)out_size;

    cc1d_init<<<NPOS * NOC / 256, 256>>>(bias, out);
    cc1d_phaseA<<<NPOS / 4, 256>>>(x, idx);

    const size_t smB = (size_t)(MT * XTP + NOC * JR) * sizeof(float);  // 66560 B
    cudaFuncSetAttribute(cc1d_phaseB, cudaFuncAttributeMaxDynamicSharedMemorySize, (int)smB);
    cc1d_phaseB<<<(NPOS / MT) * KSPL, 256, smB>>>(kern, out);
}

// round 4
// speedup vs baseline: 1.8695x; 1.0564x over previous
#include <cuda_runtime.h>
#include <math.h>

// ContinuousConv1d = Dirichlet circulant (phase A) + GEMM vs kernel^T (phase B).
// xs[p, c*64+m] = sum_k w_{f(p)}[(k-m)&63] * xwin_p[k, c]
// out[p, o]    = bias[o] + sum_j kernel[o, j] * xs[p, j]

#define NT1  4096
#define NOC  64
#define NKS  64
#define NPOS 2048
#define CM   2048          // ic*ks flattened, j = c*64 + m

__device__ float g_xs[NPOS * CM];   // 16 MB scratch (L2-resident)

static __device__ __forceinline__ unsigned long long packdup(float v) {
    unsigned long long r; asm("mov.b64 %0, {%1, %1};" : "=l"(r) : "f"(v)); return r;
}
static __device__ __forceinline__ void ffma2(unsigned long long& c,
                                             unsigned long long a, unsigned long long b) {
    asm("fma.rn.f32x2 %0, %1, %2, %0;" : "+l"(c) : "l"(a), "l"(b));
}
static __device__ __forceinline__ float2 u2f2(unsigned long long v) {
    float2 r; asm("mov.b64 {%0, %1}, %2;" : "=f"(r.x), "=f"(r.y) : "l"(v)); return r;
}

// ---------------- Phase A: 4 positions per CTA; also zeroes out ----------------
__global__ __launch_bounds__(256, 3)
void cc1d_phaseA(const float* __restrict__ x, const float* __restrict__ idxg,
                 float* __restrict__ out) {
    __shared__ float xw[4 * 2048];    // 4 windows, k-major [k][c]
    __shared__ float ws[4 * 64];      // 4 tap vectors

    const int t = threadIdx.x;
    const int pos0 = blockIdx.x * 4;
    const int b = pos0 >> 9;          // all 4 positions share batch (512 % 4 == 0)

    // zero the output slice; phase B accumulates atomically after this kernel completes
    out[blockIdx.x * 256 + t] = 0.f;

    float iv[4]; int ibase[4];
    #pragma unroll
    for (int s = 0; s < 4; ++s) { iv[s] = idxg[pos0 + s]; ibase[s] = (int)floorf(iv[s]); }

    // stage 4 windows: 2048 float4 slots
    #pragma unroll
    for (int r = 0; r < 8; ++r) {
        int s   = t + r * 256;
        int sub = s >> 9;
        int s2  = s & 511;
        int k   = s2 >> 3, c4 = s2 & 7;
        int t1  = ibase[sub] + k - (NKS / 2);
        float4 v = make_float4(0.f, 0.f, 0.f, 0.f);
        if (t1 >= 0 && t1 < NT1)
            v = reinterpret_cast<const float4*>(x)[(b * NT1 + t1) * 8 + c4];
        reinterpret_cast<float4*>(xw)[s] = v;
    }
    // Dirichlet taps: w[j] = (1/64)(1 + 2*sin(15.5a)cos(16a)/sin(a/2) + cos(32a)), a = pi(f+j)/32
    {
        int sub = t >> 6, j = t & 63;
        float f  = iv[sub] - floorf(iv[sub]);
        float u  = f + (float)j;
        float a  = u * 0.098174770424681038f;  // pi/32
        float s2 = sinf(0.5f * a);
        float wv;
        if (fabsf(s2) < 1e-5f) wv = 1.f;
        else wv = (1.f + 2.f * sinf(15.5f * a) * cosf(16.f * a) / s2 + cosf(32.f * a)) * (1.f / 64.f);
        ws[sub * 64 + j] = wv;
    }
    __syncthreads();

    // circulant: thread = (sub = t>>6, m0 = t&31, cg = (t>>5)&1 -> 16 channels)
    const int sub = t >> 6;
    const int tt  = t & 63;
    const int m0  = tt & 31;
    const int cg  = tt >> 5;
    const float* wsp = ws + sub * 64;
    const float* xwp = xw + sub * 2048 + cg * 16;

    unsigned long long acc[2][8];
    #pragma unroll
    for (int h = 0; h < 2; ++h)
        #pragma unroll
        for (int q = 0; q < 8; ++q) acc[h][q] = 0ull;

    #pragma unroll 8
    for (int k = 0; k < NKS; ++k) {
        unsigned long long wa = packdup(wsp[(k - m0) & 63]);
        unsigned long long wb = packdup(wsp[(k - m0 - 32) & 63]);
        const ulonglong2* row = reinterpret_cast<const ulonglong2*>(xwp + k * 32);
        ulonglong2 xA = row[0], xB = row[1], xC = row[2], xD = row[3];
        ffma2(acc[0][0], wa, xA.x); ffma2(acc[0][1], wa, xA.y);
        ffma2(acc[0][2], wa, xB.x); ffma2(acc[0][3], wa, xB.y);
        ffma2(acc[0][4], wa, xC.x); ffma2(acc[0][5], wa, xC.y);
        ffma2(acc[0][6], wa, xD.x); ffma2(acc[0][7], wa, xD.y);
        ffma2(acc[1][0], wb, xA.x); ffma2(acc[1][1], wb, xA.y);
        ffma2(acc[1][2], wb, xB.x); ffma2(acc[1][3], wb, xB.y);
        ffma2(acc[1][4], wb, xC.x); ffma2(acc[1][5], wb, xC.y);
        ffma2(acc[1][6], wb, xD.x); ffma2(acc[1][7], wb, xD.y);
    }

    float* dst = g_xs + (size_t)(pos0 + sub) * CM;
    #pragma unroll
    for (int h = 0; h < 2; ++h) {
        int m = m0 + h * 32;
        #pragma unroll
        for (int q = 0; q < 8; ++q) {
            float2 v = u2f2(acc[h][q]);
            dst[(cg * 16 + 2 * q) * 64 + m]     = v.x;
            dst[(cg * 16 + 2 * q + 1) * 64 + m] = v.y;
        }
    }
}

// ---------------- Phase B: out += xs @ kernel^T (+bias on split 0) ----------------
#define MTB  64            // positions per CTA
#define KSPL 8             // K-splits
#define JRB  (CM / KSPL)   // 256 j per CTA, staged as 2 chunks of 128
#define XTP  132           // xt pitch (floats)
#define KTW  128

__global__ __launch_bounds__(256, 2)
void cc1d_phaseB(const float* __restrict__ kern, const float* __restrict__ bias,
                 float* __restrict__ out) {
    extern __shared__ float smB[];
    float* xt = smB;                  // MTB x XTP
    float* kt = smB + MTB * XTP;      // NOC x KTW, xor-swizzled

    const int t  = threadIdx.x;
    const int mt = blockIdx.x >> 3;   // 0..31
    const int ks = blockIdx.x & 7;    // 0..7
    const int p0 = mt * MTB;
    const int og = t & 15;            // o = og*4 + ii
    const int pg = t >> 4;            // p = pg*4 + i

    unsigned long long acc[4][4];
    #pragma unroll
    for (int a = 0; a < 4; ++a)
        #pragma unroll
        for (int c = 0; c < 4; ++c) acc[a][c] = 0ull;

    #pragma unroll
    for (int cc = 0; cc < 2; ++cc) {
        const int jb = ks * JRB + cc * 128;
        if (cc) __syncthreads();      // previous chunk fully consumed
        #pragma unroll
        for (int r = 0; r < 8; ++r) {
            int v = t + r * 256;
            int row = v >> 5, q = v & 31;
            float4 xv = reinterpret_cast<const float4*>(g_xs + (size_t)(p0 + row) * CM + jb)[q];
            *reinterpret_cast<float4*>(xt + row * XTP + q * 4) = xv;
            float4 kv = reinterpret_cast<const float4*>(kern + (size_t)row * CM + jb)[q];
            int slot = q ^ ((row >> 2) & 15);
            *reinterpret_cast<float4*>(kt + row * KTW + slot * 4) = kv;
        }
        __syncthreads();

        const float* ktb = kt + og * 4 * KTW;
        const float* xtb = xt + pg * 4 * XTP;
        #pragma unroll 4
        for (int qq = 0; qq < 32; ++qq) {
            const int slot = qq ^ og;     // key(row) = row>>2 = og for all 4 ii
            ulonglong2 kk[4];
            #pragma unroll
            for (int ii = 0; ii < 4; ++ii)
                kk[ii] = *reinterpret_cast<const ulonglong2*>(ktb + ii * KTW + slot * 4);
            ulonglong2 xx[4];
            #pragma unroll
            for (int i = 0; i < 4; ++i)
                xx[i] = *reinterpret_cast<const ulonglong2*>(xtb + i * XTP + qq * 4);
            #pragma unroll
            for (int ii = 0; ii < 4; ++ii)
                #pragma unroll
                for (int i = 0; i < 4; ++i) {
                    ffma2(acc[ii][i], kk[ii].x, xx[i].x);
                    ffma2(acc[ii][i], kk[ii].y, xx[i].y);
                }
        }
    }

    // epilogue: accumulate K-split partials; split 0 folds the bias
    #pragma unroll
    for (int ii = 0; ii < 4; ++ii)
        #pragma unroll
        for (int i = 0; i < 4; ++i) {
            float2 v = u2f2(acc[ii][i]);
            float add = v.x + v.y;
            int o = og * 4 + ii;
            if (ks == 0) add += bias[o];
            atomicAdd(&out[(size_t)(p0 + pg * 4 + i) * NOC + o], add);
        }
}

extern "C" void kernel_launch(void* const* d_in, const int* in_sizes, int n_in,
                              void* d_out, int out_size)
{
    const float* x    = (const float*)d_in[0];
    const float* idx  = (const float*)d_in[1];
    const float* kern = (const float*)d_in[2];
    const float* bias = (const float*)d_in[3];
    float* out = (float*)d_out;
    (void)in_sizes; (void)n_in; (void)out_size;

    cc1d_phaseA<<<NPOS / 4, 256>>>(x, idx, out);

    const size_t smB = (size_t)(MTB * XTP + NOC * KTW) * sizeof(float);  // 66560 B
    cudaFuncSetAttribute(cc1d_phaseB, cudaFuncAttributeMaxDynamicSharedMemorySize, (int)smB);
    cc1d_phaseB<<<(NPOS / MTB) * KSPL, 256, smB>>>(kern, bias, out);
}

// round 6
// speedup vs baseline: 2.3770x; 1.2715x over previous
#include <cuda_runtime.h>
#include <cuda_bf16.h>
#include <math.h>
#include <stdint.h>

// ContinuousConv1d = Dirichlet circulant (phase A, FFMA2) +
//   GEMM vs kernel^T (phase B, mma.sync bf16 3-term split, fp32 accum).
// xs[p, c*64+m] = sum_k w_{f(p)}[(k-m)&63] * xwin_p[k, c]
// out[p, o]    = bias[o] + sum_j kernel[o, j] * xs[p, j]

#define NT1  4096
#define NOC  64
#define NKS  64
#define NPOS 2048
#define CM   2048

__device__ __nv_bfloat16 g_xh[NPOS * CM];   // 8 MB hi scratch
__device__ __nv_bfloat16 g_xl[NPOS * CM];   // 8 MB lo scratch

static __device__ __forceinline__ unsigned long long packdup(float v) {
    unsigned long long r; asm("mov.b64 %0, {%1, %1};" : "=l"(r) : "f"(v)); return r;
}
static __device__ __forceinline__ void ffma2(unsigned long long& c,
                                             unsigned long long a, unsigned long long b) {
    asm("fma.rn.f32x2 %0, %1, %2, %0;" : "+l"(c) : "l"(a), "l"(b));
}
static __device__ __forceinline__ float2 u2f2(unsigned long long v) {
    float2 r; asm("mov.b64 {%0, %1}, %2;" : "=f"(r.x), "=f"(r.y) : "l"(v)); return r;
}

// ---------------- Phase A: 4 positions per CTA; writes bf16 hi/lo; zeroes out ----------------
__global__ __launch_bounds__(256, 3)
void cc1d_phaseA(const float* __restrict__ x, const float* __restrict__ idxg,
                 float* __restrict__ out) {
    __shared__ float xw[4 * 2048];
    __shared__ float ws[4 * 64];

    const int t = threadIdx.x;
    const int pos0 = blockIdx.x * 4;
    const int b = pos0 >> 9;

    out[blockIdx.x * 256 + t] = 0.f;   // phase B accumulates atomically

    float iv[4]; int ibase[4];
    #pragma unroll
    for (int s = 0; s < 4; ++s) { iv[s] = idxg[pos0 + s]; ibase[s] = (int)floorf(iv[s]); }

    #pragma unroll
    for (int r = 0; r < 8; ++r) {
        int s   = t + r * 256;
        int sub = s >> 9;
        int s2  = s & 511;
        int k   = s2 >> 3, c4 = s2 & 7;
        int t1  = ibase[sub] + k - (NKS / 2);
        float4 v = make_float4(0.f, 0.f, 0.f, 0.f);
        if (t1 >= 0 && t1 < NT1)
            v = reinterpret_cast<const float4*>(x)[(b * NT1 + t1) * 8 + c4];
        reinterpret_cast<float4*>(xw)[s] = v;
    }
    {   // Dirichlet taps: w[j] = (1/64)(1 + 2 sin(15.5a)cos(16a)/sin(a/2) + cos(32a)), a = pi(f+j)/32
        int sub = t >> 6, j = t & 63;
        float f  = iv[sub] - floorf(iv[sub]);
        float u  = f + (float)j;
        float a  = u * 0.098174770424681038f;
        float s2 = sinf(0.5f * a);
        float wv;
        if (fabsf(s2) < 1e-5f) wv = 1.f;
        else wv = (1.f + 2.f * sinf(15.5f * a) * cosf(16.f * a) / s2 + cosf(32.f * a)) * (1.f / 64.f);
        ws[sub * 64 + j] = wv;
    }
    __syncthreads();

    const int sub = t >> 6;
    const int tt  = t & 63;
    const int m0  = tt & 31;
    const int cg  = tt >> 5;
    const float* wsp = ws + sub * 64;
    const float* xwp = xw + sub * 2048 + cg * 16;

    unsigned long long acc[2][8];
    #pragma unroll
    for (int h = 0; h < 2; ++h)
        #pragma unroll
        for (int q = 0; q < 8; ++q) acc[h][q] = 0ull;

    #pragma unroll 8
    for (int k = 0; k < NKS; ++k) {
        unsigned long long wa = packdup(wsp[(k - m0) & 63]);
        unsigned long long wb = packdup(wsp[(k - m0 - 32) & 63]);
        const ulonglong2* row = reinterpret_cast<const ulonglong2*>(xwp + k * 32);
        ulonglong2 xA = row[0], xB = row[1], xC = row[2], xD = row[3];
        ffma2(acc[0][0], wa, xA.x); ffma2(acc[0][1], wa, xA.y);
        ffma2(acc[0][2], wa, xB.x); ffma2(acc[0][3], wa, xB.y);
        ffma2(acc[0][4], wa, xC.x); ffma2(acc[0][5], wa, xC.y);
        ffma2(acc[0][6], wa, xD.x); ffma2(acc[0][7], wa, xD.y);
        ffma2(acc[1][0], wb, xA.x); ffma2(acc[1][1], wb, xA.y);
        ffma2(acc[1][2], wb, xB.x); ffma2(acc[1][3], wb, xB.y);
        ffma2(acc[1][4], wb, xC.x); ffma2(acc[1][5], wb, xC.y);
        ffma2(acc[1][6], wb, xD.x); ffma2(acc[1][7], wb, xD.y);
    }

    __nv_bfloat16* dh = g_xh + (pos0 + sub) * CM;
    __nv_bfloat16* dl = g_xl + (pos0 + sub) * CM;
    #pragma unroll
    for (int h = 0; h < 2; ++h) {
        int m = m0 + h * 32;
        #pragma unroll
        for (int q = 0; q < 8; ++q) {
            float2 v = u2f2(acc[h][q]);
            int i0 = (cg * 16 + 2 * q) * 64 + m;
            __nv_bfloat16 hx = __float2bfloat16_rn(v.x);
            __nv_bfloat16 hy = __float2bfloat16_rn(v.y);
            dh[i0]      = hx;
            dh[i0 + 64] = hy;
            dl[i0]      = __float2bfloat16_rn(v.x - __bfloat162float(hx));
            dl[i0 + 64] = __float2bfloat16_rn(v.y - __bfloat162float(hy));
        }
    }
}

// ---------------- Phase B: mma.sync bf16 GEMM, fp32-split ----------------
#define MB   128              // M per CTA
#define KSPL 8
#define KC   (CM / KSPL)      // 256 K per CTA
// smem: bf16 tiles, rows of 256 bf16 = 512 B = 32 x 16B units, unit XOR-swizzled by (row&7)
#define SMB_AH 0
#define SMB_AL (MB * 512)                 // 65536
#define SMB_BH (SMB_AL + MB * 512)        // 131072
#define SMB_BL (SMB_BH + NOC * 512)       // 163840
#define SMB_TOT (SMB_BL + NOC * 512)      // 196608 B

static __device__ __forceinline__ uint32_t smem_u32(const void* p) {
    uint32_t a;
    asm("{ .reg .u64 t; cvta.to.shared.u64 t, %1; cvt.u32.u64 %0, t; }" : "=r"(a) : "l"(p));
    return a;
}
static __device__ __forceinline__ void ldm4(uint32_t* r, uint32_t addr) {
    asm volatile("ldmatrix.sync.aligned.m8n8.x4.shared.b16 {%0,%1,%2,%3}, [%4];"
                 : "=r"(r[0]), "=r"(r[1]), "=r"(r[2]), "=r"(r[3]) : "r"(addr));
}
static __device__ __forceinline__ void mma_bf16(float* d, const uint32_t* a,
                                                uint32_t b0, uint32_t b1) {
    asm volatile("mma.sync.aligned.m16n8k16.row.col.f32.bf16.bf16.f32 "
                 "{%0,%1,%2,%3}, {%4,%5,%6,%7}, {%8,%9}, {%0,%1,%2,%3};"
                 : "+f"(d[0]), "+f"(d[1]), "+f"(d[2]), "+f"(d[3])
                 : "r"(a[0]), "r"(a[1]), "r"(a[2]), "r"(a[3]), "r"(b0), "r"(b1));
}

__global__ __launch_bounds__(256, 1)
void cc1d_phaseB(const float* __restrict__ kern, const float* __restrict__ bias,
                 float* __restrict__ out) {
    extern __shared__ char smB[];
    const uint32_t sb = smem_u32(smB);
    const int t = threadIdx.x, wid = t >> 5, lane = t & 31;
    const int mt = blockIdx.x >> 3;
    const int ks = blockIdx.x & 7;
    const int p0 = mt * MB;
    const int k0 = ks * KC;

    // ---- stage A hi/lo (bf16 copy, swizzled) : 4096 16B units each ----
    #pragma unroll 4
    for (int i = 0; i < 16; ++i) {
        int u   = t + i * 256;
        int row = u >> 5;
        int un  = u & 31;
        uint32_t off = (uint32_t)row * 512u + (uint32_t)((un ^ (row & 7)) << 4);
        *reinterpret_cast<uint4*>(smB + SMB_AH + off) =
            *reinterpret_cast<const uint4*>(g_xh + (p0 + row) * CM + k0 + un * 8);
        *reinterpret_cast<uint4*>(smB + SMB_AL + off) =
            *reinterpret_cast<const uint4*>(g_xl + (p0 + row) * CM + k0 + un * 8);
    }
    // ---- stage B hi/lo (split fp32 -> bf16, swizzled) : 2048 16B units each ----
    #pragma unroll 4
    for (int i = 0; i < 8; ++i) {
        int u   = t + i * 256;
        int row = u >> 5;
        int un  = u & 31;
        const float4* src = reinterpret_cast<const float4*>(kern + row * CM + k0 + un * 8);
        float4 f0 = src[0], f1 = src[1];
        float fs[8] = {f0.x, f0.y, f0.z, f0.w, f1.x, f1.y, f1.z, f1.w};
        uint32_t hw[4], lw[4];
        #pragma unroll
        for (int q = 0; q < 4; ++q) {
            float a = fs[2 * q], c = fs[2 * q + 1];
            __nv_bfloat162 hh = __floats2bfloat162_rn(a, c);
            float la = a - __bfloat162float(hh.x);
            float lc = c - __bfloat162float(hh.y);
            __nv_bfloat162 ll = __floats2bfloat162_rn(la, lc);
            hw[q] = *reinterpret_cast<uint32_t*>(&hh);
            lw[q] = *reinterpret_cast<uint32_t*>(&ll);
        }
        uint32_t off = (uint32_t)row * 512u + (uint32_t)((un ^ (row & 7)) << 4);
        *reinterpret_cast<uint4*>(smB + SMB_BH + off) = make_uint4(hw[0], hw[1], hw[2], hw[3]);
        *reinterpret_cast<uint4*>(smB + SMB_BL + off) = make_uint4(lw[0], lw[1], lw[2], lw[3]);
    }
    __syncthreads();

    // ---- per-lane ldmatrix address precomputation ----
    // A (x4): r = rowbase + (lane&15), k-unit add (lane>>4)
    const int arow = wid * 16 + (lane & 15);
    const uint32_t aBaseH = sb + SMB_AH + (uint32_t)arow * 512u;
    const uint32_t aBaseL = sb + SMB_AL + (uint32_t)arow * 512u;
    const int aXor = arow & 7;
    const int aKU  = lane >> 4;
    // B (x4, 2 n-tiles per load): n = g*16 + (lane&7) + ((lane>>4)<<3), k-unit add (lane>>3)&1
    const int nIdx = (lane & 7) + ((lane >> 4) << 3);
    const int bKU  = (lane >> 3) & 1;
    uint32_t bBaseH[4], bBaseL[4]; int bXor[4];
    #pragma unroll
    for (int g = 0; g < 4; ++g) {
        int nrow = g * 16 + nIdx;
        bBaseH[g] = sb + SMB_BH + (uint32_t)nrow * 512u;
        bBaseL[g] = sb + SMB_BL + (uint32_t)nrow * 512u;
        bXor[g] = nrow & 7;
    }

    float acc[8][4];
    #pragma unroll
    for (int nt = 0; nt < 8; ++nt)
        #pragma unroll
        for (int q = 0; q < 4; ++q) acc[nt][q] = 0.f;

    #pragma unroll 4
    for (int s = 0; s < KC / 16; ++s) {
        const int kb8 = s * 2;
        uint32_t ah[4], al[4];
        {
            uint32_t sw = (uint32_t)(((kb8 + aKU) ^ aXor) << 4);
            ldm4(ah, aBaseH + sw);
            ldm4(al, aBaseL + sw);
        }
        uint32_t bh[4][4], bl[4][4];
        #pragma unroll
        for (int g = 0; g < 4; ++g) {
            uint32_t sw = (uint32_t)(((kb8 + bKU) ^ bXor[g]) << 4);
            ldm4(bh[g], bBaseH[g] + sw);
            ldm4(bl[g], bBaseL[g] + sw);
        }
        #pragma unroll
        for (int g = 0; g < 4; ++g) {
            mma_bf16(acc[g * 2],     ah, bh[g][0], bh[g][1]);
            mma_bf16(acc[g * 2],     al, bh[g][0], bh[g][1]);
            mma_bf16(acc[g * 2],     ah, bl[g][0], bl[g][1]);
            mma_bf16(acc[g * 2 + 1], ah, bh[g][2], bh[g][3]);
            mma_bf16(acc[g * 2 + 1], al, bh[g][2], bh[g][3]);
            mma_bf16(acc[g * 2 + 1], ah, bl[g][2], bl[g][3]);
        }
    }

    // ---- epilogue: atomic accumulate (bias folded into split 0) ----
    const int quad = lane >> 2;
    const int qid  = lane & 3;
    const int r0 = p0 + wid * 16 + quad;
    #pragma unroll
    for (int nt = 0; nt < 8; ++nt) {
        int c0 = nt * 8 + qid * 2;
        float b0 = 0.f, b1 = 0.f;
        if (ks == 0) { b0 = bias[c0]; b1 = bias[c0 + 1]; }
        atomicAdd(&out[r0 * NOC + c0],           acc[nt][0] + b0);
        atomicAdd(&out[r0 * NOC + c0 + 1],       acc[nt][1] + b1);
        atomicAdd(&out[(r0 + 8) * NOC + c0],     acc[nt][2] + b0);
        atomicAdd(&out[(r0 + 8) * NOC + c0 + 1], acc[nt][3] + b1);
    }
}

extern "C" void kernel_launch(void* const* d_in, const int* in_sizes, int n_in,
                              void* d_out, int out_size)
{
    const float* x    = (const float*)d_in[0];
    const float* idx  = (const float*)d_in[1];
    const float* kern = (const float*)d_in[2];
    const float* bias = (const float*)d_in[3];
    float* out = (float*)d_out;
    (void)in_sizes; (void)n_in; (void)out_size;

    cc1d_phaseA<<<NPOS / 4, 256>>>(x, idx, out);

    cudaFuncSetAttribute(cc1d_phaseB, cudaFuncAttributeMaxDynamicSharedMemorySize, SMB_TOT);
    cc1d_phaseB<<<(NPOS / MB) * KSPL, 256, SMB_TOT>>>(kern, bias, out);
}

// round 7
// speedup vs baseline: 2.3795x; 1.0010x over previous
#include <cuda_runtime.h>
#include <cuda_bf16.h>
#include <math.h>
#include <stdint.h>

// ContinuousConv1d, all-tensor-core:
//  phase A: per position p, xs_p = W(f_p) @ xwin_p  (64x64 circulant x 64x32), HMMA 3-term bf16 split
//  phase B: out[p,o] = bias[o] + sum_j xs[p,j] kernel[o,j], HMMA 3-term bf16 split
// Storage layout of xs / kernel-splits is a fixed permutation sigma of j=c*64+m (fragment order);
// both sides use the same sigma so the dot product is unchanged.

#define NT1  4096
#define NOC  64
#define NPOS 2048

__device__ uint32_t g_xh[NPOS * 1024];   // bf16x2 words, sigma order
__device__ uint32_t g_xl[NPOS * 1024];
__device__ uint32_t g_kh[NOC * 1024];
__device__ uint32_t g_kl[NOC * 1024];

static __device__ __forceinline__ uint32_t smem_u32(const void* p) {
    uint32_t a;
    asm("{ .reg .u64 t; cvta.to.shared.u64 t, %1; cvt.u32.u64 %0, t; }" : "=r"(a) : "l"(p));
    return a;
}
static __device__ __forceinline__ void ldm4(uint32_t* r, uint32_t addr) {
    asm volatile("ldmatrix.sync.aligned.m8n8.x4.shared.b16 {%0,%1,%2,%3}, [%4];"
                 : "=r"(r[0]), "=r"(r[1]), "=r"(r[2]), "=r"(r[3]) : "r"(addr));
}
static __device__ __forceinline__ void mma_bf16(float* d, const uint32_t* a,
                                                uint32_t b0, uint32_t b1) {
    asm volatile("mma.sync.aligned.m16n8k16.row.col.f32.bf16.bf16.f32 "
                 "{%0,%1,%2,%3}, {%4,%5,%6,%7}, {%8,%9}, {%0,%1,%2,%3};"
                 : "+f"(d[0]), "+f"(d[1]), "+f"(d[2]), "+f"(d[3])
                 : "r"(a[0]), "r"(a[1]), "r"(a[2]), "r"(a[3]), "r"(b0), "r"(b1));
}
// split (a,b) fp32 -> packed bf16x2 hi word + lo word (low half = a)
static __device__ __forceinline__ void split2(float a, float b, uint32_t& hw, uint32_t& lw) {
    __nv_bfloat162 h2 = __floats2bfloat162_rn(a, b);
    float ra = a - __bfloat162float(h2.x);
    float rb = b - __bfloat162float(h2.y);
    __nv_bfloat162 l2 = __floats2bfloat162_rn(ra, rb);
    hw = *reinterpret_cast<uint32_t*>(&h2);
    lw = *reinterpret_cast<uint32_t*>(&l2);
}

// ---------------- Phase A smem layout (bytes) ----------------
#define SA_XWF 0                    // 4 x [64][33] fp32 = 33792
#define SA_TR  33792                // per pos: hi bf16[64] (128B) + lo bf16[64] (128B) = 256B; x4 = 1024
#define SA_TP  34816                // per pos: pack1 hi u32[32] (128B) + lo (128B) = 256B; x4 = 1024
#define SA_WT  35840                // per pos: W hi 64x128B (8192) + lo 8192 = 16384; x4 = 65536
#define SA_BT  (SA_WT + 65536)      // per pos: X^T hi 32x128B (4096) + lo 4096 = 8192; x4 = 32768
#define SA_TOT (SA_BT + 32768)      // 134144

__global__ __launch_bounds__(256, 1)
void cc1d_phaseA(const float* __restrict__ x, const float* __restrict__ idxg,
                 const float* __restrict__ kern, float* __restrict__ out) {
    extern __shared__ char sm[];
    const int t = threadIdx.x;
    const int wid = t >> 5, lane = t & 31;

    // ---------- tail CTAs: write kernel splits in sigma order ----------
    if (blockIdx.x >= 512) {
        int wb = blockIdx.x - 512;          // 0..31
        #pragma unroll
        for (int rr = 0; rr < 2; ++rr) {
            int o = wb * 2 + rr;
            #pragma unroll
            for (int i = 0; i < 4; ++i) {
                int W = t + i * 256;        // word 0..1023
                int mh = W >> 9, T = (W >> 6) & 7, r = (W >> 5) & 1, L = W & 31;
                int tm = T >> 2, tn = T & 3, q = L >> 2, id = L & 3;
                int m = mh * 32 + tm * 16 + r * 8 + q;
                int c = tn * 8 + id * 2;
                int j0 = c * 64 + m;
                float f0 = kern[o * 2048 + j0];
                float f1 = kern[o * 2048 + j0 + 64];
                uint32_t hw, lw; split2(f0, f1, hw, lw);
                g_kh[o * 1024 + W] = hw;
                g_kl[o * 1024 + W] = lw;
            }
        }
        return;
    }

    const int pos0 = blockIdx.x * 4;
    const int b = pos0 >> 9;

    out[blockIdx.x * 256 + t] = 0.f;        // phase B accumulates atomically

    float iv[4]; int ibase[4];
    #pragma unroll
    for (int s = 0; s < 4; ++s) { iv[s] = idxg[pos0 + s]; ibase[s] = (int)floorf(iv[s]); }

    // ---------- stage 4 windows as [k][33] fp32 ----------
    #pragma unroll
    for (int i = 0; i < 8; ++i) {
        int s  = t + i * 256;               // 0..2047 float4 slots
        int p  = s >> 9;
        int s2 = s & 511;
        int k  = s2 >> 3, c4 = s2 & 7;
        int t1 = ibase[p] + k - 32;
        float4 v = make_float4(0.f, 0.f, 0.f, 0.f);
        if (t1 >= 0 && t1 < NT1)
            v = reinterpret_cast<const float4*>(x)[(b * NT1 + t1) * 8 + c4];
        float* dst = reinterpret_cast<float*>(sm + SA_XWF) + p * 2112 + k * 33 + c4 * 4;
        dst[0] = v.x; dst[1] = v.y; dst[2] = v.z; dst[3] = v.w;
    }
    // ---------- taps (Dirichlet), split to bf16 hi/lo ----------
    {
        int p = t >> 6, j = t & 63;
        float f  = iv[p] - floorf(iv[p]);
        float u  = f + (float)j;
        float a  = u * 0.098174770424681038f;   // pi/32
        float s2 = sinf(0.5f * a);
        float wv;
        if (fabsf(s2) < 1e-5f) wv = 1.f;
        else wv = (1.f + 2.f * sinf(15.5f * a) * cosf(16.f * a) / s2 + cosf(32.f * a)) * (1.f / 64.f);
        __nv_bfloat16 hv = __float2bfloat16_rn(wv);
        __nv_bfloat16 lv = __float2bfloat16_rn(wv - __bfloat162float(hv));
        reinterpret_cast<uint16_t*>(sm + SA_TR + p * 256)[j]       = *reinterpret_cast<uint16_t*>(&hv);
        reinterpret_cast<uint16_t*>(sm + SA_TR + p * 256 + 128)[j] = *reinterpret_cast<uint16_t*>(&lv);
    }
    __syncthreads();

    // ---------- odd-offset packed tap tables ----------
    if (t < 128) {
        int p = t >> 5, w = t & 31;
        const uint16_t* rh = reinterpret_cast<const uint16_t*>(sm + SA_TR + p * 256);
        const uint16_t* rl = rh + 64;
        uint32_t ph = (uint32_t)rh[2 * w + 1] | ((uint32_t)rh[(2 * w + 2) & 63] << 16);
        uint32_t pl = (uint32_t)rl[2 * w + 1] | ((uint32_t)rl[(2 * w + 2) & 63] << 16);
        reinterpret_cast<uint32_t*>(sm + SA_TP + p * 256)[w]       = ph;
        reinterpret_cast<uint32_t*>(sm + SA_TP + p * 256 + 128)[w] = pl;
    }
    __syncthreads();

    const int p  = wid >> 1;                // warp's position
    const int mh = wid & 1;                 // m-half

    // ---------- build W tiles (rows m = mh*32 .. +31) ----------
    {
        const uint32_t* rawH = reinterpret_cast<const uint32_t*>(sm + SA_TR + p * 256);
        const uint32_t* rawL = reinterpret_cast<const uint32_t*>(sm + SA_TR + p * 256 + 128);
        const uint32_t* p1H  = reinterpret_cast<const uint32_t*>(sm + SA_TP + p * 256);
        const uint32_t* p1L  = reinterpret_cast<const uint32_t*>(sm + SA_TP + p * 256 + 128);
        char* wtH = sm + SA_WT + p * 16384;
        char* wtL = wtH + 8192;
        #pragma unroll 4
        for (int rr = 0; rr < 32; ++rr) {
            int m = mh * 32 + rr;
            uint32_t wh, wl;
            if (m & 1) {
                int u = (lane - ((m + 1) >> 1)) & 31;
                wh = p1H[u]; wl = p1L[u];
            } else {
                int u = (lane - (m >> 1)) & 31;
                wh = rawH[u]; wl = rawL[u];
            }
            uint32_t off = (uint32_t)m * 128u + (uint32_t)(((lane >> 2) ^ (m & 7)) << 4)
                         + (uint32_t)((lane & 3) << 2);
            *reinterpret_cast<uint32_t*>(wtH + off) = wh;
            *reinterpret_cast<uint32_t*>(wtL + off) = wl;
        }
    }
    // ---------- build X^T tiles [c][k] bf16 hi/lo ----------
    {
        int l64 = (wid & 1) * 32 + lane;
        int c   = l64 >> 1;
        int kh  = (l64 & 1) * 32;
        const float* col = reinterpret_cast<const float*>(sm + SA_XWF) + p * 2112 + c;
        char* btH = sm + SA_BT + p * 8192;
        char* btL = btH + 4096;
        #pragma unroll
        for (int wq = 0; wq < 16; ++wq) {
            float a0 = col[(kh + 2 * wq) * 33];
            float a1 = col[(kh + 2 * wq + 1) * 33];
            uint32_t hw, lw; split2(a0, a1, hw, lw);
            int word = (kh >> 1) + wq;      // 0..31 in row
            uint32_t off = (uint32_t)c * 128u + (uint32_t)(((word >> 2) ^ (c & 7)) << 4)
                         + (uint32_t)((word & 3) << 2);
            *reinterpret_cast<uint32_t*>(btH + off) = hw;
            *reinterpret_cast<uint32_t*>(btL + off) = lw;
        }
    }
    __syncthreads();

    // ---------- MMA: warp computes xs rows m = mh*32..+31, all 32 c ----------
    const uint32_t sb = smem_u32(sm);
    const uint32_t aH = sb + SA_WT + p * 16384;
    const uint32_t aL = aH + 8192;
    const uint32_t bH = sb + SA_BT + p * 8192;
    const uint32_t bL = bH + 4096;
    const int arow0 = mh * 32 + (lane & 15);
    const int aKU   = lane >> 4;
    const int nIdx  = (lane & 7) + ((lane >> 4) << 3);
    const int bKU   = (lane >> 3) & 1;

    float acc[2][4][4];
    #pragma unroll
    for (int tm = 0; tm < 2; ++tm)
        #pragma unroll
        for (int tn = 0; tn < 4; ++tn)
            #pragma unroll
            for (int q = 0; q < 4; ++q) acc[tm][tn][q] = 0.f;

    #pragma unroll
    for (int s = 0; s < 4; ++s) {
        uint32_t ah[2][4], al[2][4];
        #pragma unroll
        for (int tm = 0; tm < 2; ++tm) {
            int ar = arow0 + tm * 16;
            uint32_t sw = (uint32_t)((((s * 2) + aKU) ^ (ar & 7)) << 4);
            ldm4(ah[tm], aH + (uint32_t)ar * 128u + sw);
            ldm4(al[tm], aL + (uint32_t)ar * 128u + sw);
        }
        uint32_t bh[2][4], bl[2][4];
        #pragma unroll
        for (int g = 0; g < 2; ++g) {
            int nr = g * 16 + nIdx;
            uint32_t sw = (uint32_t)((((s * 2) + bKU) ^ (nr & 7)) << 4);
            ldm4(bh[g], bH + (uint32_t)nr * 128u + sw);
            ldm4(bl[g], bL + (uint32_t)nr * 128u + sw);
        }
        #pragma unroll
        for (int tm = 0; tm < 2; ++tm)
            #pragma unroll
            for (int tn = 0; tn < 4; ++tn) {
                int g = tn >> 1, q0 = (tn & 1) * 2;
                mma_bf16(acc[tm][tn], ah[tm], bh[g][q0], bh[g][q0 + 1]);
                mma_bf16(acc[tm][tn], al[tm], bh[g][q0], bh[g][q0 + 1]);
                mma_bf16(acc[tm][tn], ah[tm], bl[g][q0], bl[g][q0 + 1]);
            }
    }

    // ---------- epilogue: store fragments in sigma order (coalesced) ----------
    uint32_t* oh = g_xh + (pos0 + p) * 1024 + mh * 512;
    uint32_t* ol = g_xl + (pos0 + p) * 1024 + mh * 512;
    #pragma unroll
    for (int tm = 0; tm < 2; ++tm)
        #pragma unroll
        for (int tn = 0; tn < 4; ++tn) {
            int T = tm * 4 + tn;
            #pragma unroll
            for (int r = 0; r < 2; ++r) {
                uint32_t hw, lw;
                split2(acc[tm][tn][2 * r], acc[tm][tn][2 * r + 1], hw, lw);
                oh[T * 64 + r * 32 + lane] = hw;
                ol[T * 64 + r * 32 + lane] = lw;
            }
        }
}

// ---------------- Phase B: out += xs @ kernel^T (sigma order), HMMA ----------------
#define SB_AH 0
#define SB_AL 16384
#define SB_BH 32768
#define SB_BL 49152
#define SB_TOT 65536

__global__ __launch_bounds__(256, 3)
void cc1d_phaseB(const float* __restrict__ bias, float* __restrict__ out) {
    extern __shared__ char sm[];
    const uint32_t sb = smem_u32(sm);
    const int t = threadIdx.x, wid = t >> 5, lane = t & 31;
    const int mt = blockIdx.x >> 3;
    const int ks = blockIdx.x & 7;
    const int p0 = mt * 64;

    const int mtile = wid >> 1;             // m16 tile 0..3
    const int nh    = wid & 1;              // n-half (cols 0-31 / 32-63)
    const int arow  = mtile * 16 + (lane & 15);
    const int aKU   = lane >> 4;
    const int nIdx  = (lane & 7) + ((lane >> 4) << 3);
    const int bKU   = (lane >> 3) & 1;

    float acc[4][4];
    #pragma unroll
    for (int tn = 0; tn < 4; ++tn)
        #pragma unroll
        for (int q = 0; q < 4; ++q) acc[tn][q] = 0.f;

    #pragma unroll
    for (int cc = 0; cc < 2; ++cc) {
        if (cc) __syncthreads();
        const int wb0 = ks * 128 + cc * 64;     // word base within each row's 1024
        // stage: 4096 16B units (A hi/lo + B hi/lo), 16 per thread
        #pragma unroll
        for (int i = 0; i < 16; ++i) {
            int u    = t + i * 256;
            int isB  = u >> 11;
            int rem  = u & 2047;
            int hl   = rem >> 10;
            int rem2 = rem & 1023;
            int row  = rem2 >> 4;
            int un   = rem2 & 15;
            const uint32_t* src = isB ? (hl ? g_kl : g_kh) : (hl ? g_xl : g_xh);
            int srow = isB ? row : (p0 + row);
            uint4 v = *reinterpret_cast<const uint4*>(src + srow * 1024 + wb0 + un * 4);
            uint32_t doff = (uint32_t)(isB * 32768 + hl * 16384)
                          + (uint32_t)row * 256u + (uint32_t)((un ^ (row & 7)) << 4);
            *reinterpret_cast<uint4*>(sm + doff) = v;
        }
        __syncthreads();

        #pragma unroll
        for (int s = 0; s < 8; ++s) {
            uint32_t ah[4], al[4];
            {
                uint32_t sw = (uint32_t)((((s * 2) + aKU) ^ (arow & 7)) << 4);
                ldm4(ah, sb + SB_AH + (uint32_t)arow * 256u + sw);
                ldm4(al, sb + SB_AL + (uint32_t)arow * 256u + sw);
            }
            uint32_t bh[2][4], bl[2][4];
            #pragma unroll
            for (int g = 0; g < 2; ++g) {
                int nr = nh * 32 + g * 16 + nIdx;
                uint32_t sw = (uint32_t)((((s * 2) + bKU) ^ (nr & 7)) << 4);
                ldm4(bh[g], sb + SB_BH + (uint32_t)nr * 256u + sw);
                ldm4(bl[g], sb + SB_BL + (uint32_t)nr * 256u + sw);
            }
            #pragma unroll
            for (int tn = 0; tn < 4; ++tn) {
                int g = tn >> 1, q0 = (tn & 1) * 2;
                mma_bf16(acc[tn], ah, bh[g][q0], bh[g][q0 + 1]);
                mma_bf16(acc[tn], al, bh[g][q0], bh[g][q0 + 1]);
                mma_bf16(acc[tn], ah, bl[g][q0], bl[g][q0 + 1]);
            }
        }
    }

    // ---------- epilogue: atomic accumulate, bias folded on split 0 ----------
    const int quad = lane >> 2, id = lane & 3;
    const int r0 = p0 + mtile * 16 + quad;
    #pragma unroll
    for (int tn = 0; tn < 4; ++tn) {
        int c0 = nh * 32 + tn * 8 + id * 2;
        float b0 = 0.f, b1 = 0.f;
        if (ks == 0) { b0 = bias[c0]; b1 = bias[c0 + 1]; }
        atomicAdd(&out[r0 * NOC + c0],           acc[tn][0] + b0);
        atomicAdd(&out[r0 * NOC + c0 + 1],       acc[tn][1] + b1);
        atomicAdd(&out[(r0 + 8) * NOC + c0],     acc[tn][2] + b0);
        atomicAdd(&out[(r0 + 8) * NOC + c0 + 1], acc[tn][3] + b1);
    }
}

extern "C" void kernel_launch(void* const* d_in, const int* in_sizes, int n_in,
                              void* d_out, int out_size)
{
    const float* x    = (const float*)d_in[0];
    const float* idx  = (const float*)d_in[1];
    const float* kern = (const float*)d_in[2];
    const float* bias = (const float*)d_in[3];
    float* out = (float*)d_out;
    (void)in_sizes; (void)n_in; (void)out_size;

    cudaFuncSetAttribute(cc1d_phaseA, cudaFuncAttributeMaxDynamicSharedMemorySize, SA_TOT);
    cc1d_phaseA<<<512 + 32, 256, SA_TOT>>>(x, idx, kern, out);

    cudaFuncSetAttribute(cc1d_phaseB, cudaFuncAttributeMaxDynamicSharedMemorySize, SB_TOT);
    cc1d_phaseB<<<32 * 8, 256, SB_TOT>>>(bias, out);
}

// round 8
// speedup vs baseline: 3.4524x; 1.4509x over previous
#include <cuda_runtime.h>
#include <cuda_bf16.h>
#include <math.h>
#include <stdint.h>

// ContinuousConv1d, all-tensor-core:
//  phase A: xs_p = W(f_p) @ xwin_p  (64x64 circulant x 64x32), HMMA 3-term bf16 split
//  phase B: out[p,o] = bias[o] + sum_j xs[p,j] kernel[o,j], HMMA 3-term, cp.async pipelined
// xs / kernel splits stored in a fixed fragment permutation sigma of j (identical on both
// sides, so the dot product is unchanged).

#define NT1  4096
#define NOC  64
#define NPOS 2048

__device__ uint32_t g_xh[NPOS * 1024];   // bf16x2 words, sigma order
__device__ uint32_t g_xl[NPOS * 1024];
__device__ uint32_t g_kh[NOC * 1024];
__device__ uint32_t g_kl[NOC * 1024];

static __device__ __forceinline__ uint32_t smem_u32(const void* p) {
    uint32_t a;
    asm("{ .reg .u64 t; cvta.to.shared.u64 t, %1; cvt.u32.u64 %0, t; }" : "=r"(a) : "l"(p));
    return a;
}
static __device__ __forceinline__ void ldm4(uint32_t* r, uint32_t addr) {
    asm volatile("ldmatrix.sync.aligned.m8n8.x4.shared.b16 {%0,%1,%2,%3}, [%4];"
                 : "=r"(r[0]), "=r"(r[1]), "=r"(r[2]), "=r"(r[3]) : "r"(addr));
}
static __device__ __forceinline__ void ldm4t(uint32_t* r, uint32_t addr) {
    asm volatile("ldmatrix.sync.aligned.m8n8.x4.trans.shared.b16 {%0,%1,%2,%3}, [%4];"
                 : "=r"(r[0]), "=r"(r[1]), "=r"(r[2]), "=r"(r[3]) : "r"(addr));
}
static __device__ __forceinline__ void mma_bf16(float* d, const uint32_t* a,
                                                uint32_t b0, uint32_t b1) {
    asm volatile("mma.sync.aligned.m16n8k16.row.col.f32.bf16.bf16.f32 "
                 "{%0,%1,%2,%3}, {%4,%5,%6,%7}, {%8,%9}, {%0,%1,%2,%3};"
                 : "+f"(d[0]), "+f"(d[1]), "+f"(d[2]), "+f"(d[3])
                 : "r"(a[0]), "r"(a[1]), "r"(a[2]), "r"(a[3]), "r"(b0), "r"(b1));
}
static __device__ __forceinline__ void split2(float a, float b, uint32_t& hw, uint32_t& lw) {
    __nv_bfloat162 h2 = __floats2bfloat162_rn(a, b);
    float ra = a - __bfloat162float(h2.x);
    float rb = b - __bfloat162float(h2.y);
    __nv_bfloat162 l2 = __floats2bfloat162_rn(ra, rb);
    hw = *reinterpret_cast<uint32_t*>(&h2);
    lw = *reinterpret_cast<uint32_t*>(&l2);
}
static __device__ __forceinline__ void cpasync16(uint32_t dst, const void* src) {
    asm volatile("cp.async.cg.shared.global [%0], [%1], 16;" :: "r"(dst), "l"(src));
}

// ---------------- Phase A smem layout (bytes) ----------------
// X: per pos hi 64x80 (5120) + lo 5120 = 10240; x2 pos = 20480
// W: per pos hi 64x128 (8192) + lo 8192 = 16384; x2 pos = 32768
// taps raw: 2x256, packed: 2x256
#define SA_X   0
#define SA_W   20480
#define SA_TR  53248
#define SA_TP  53760
#define SA_TOT 54272

__global__ __launch_bounds__(256, 3)
void cc1d_phaseA(const float* __restrict__ x, const float* __restrict__ idxg,
                 const float* __restrict__ kern, float* __restrict__ out) {
    extern __shared__ char sm[];
    const int t = threadIdx.x;
    const int wid = t >> 5, lane = t & 31;

    // ---------- tail CTAs: write kernel splits in sigma order ----------
    if (blockIdx.x >= 1024) {
        int wb = blockIdx.x - 1024;         // 0..31
        #pragma unroll
        for (int rr = 0; rr < 2; ++rr) {
            int o = wb * 2 + rr;
            #pragma unroll
            for (int i = 0; i < 4; ++i) {
                int W = t + i * 256;        // word 0..1023
                int mh = W >> 9, T = (W >> 6) & 7, r = (W >> 5) & 1, L = W & 31;
                int tm = T >> 2, tn = T & 3, q = L >> 2, id = L & 3;
                int m = mh * 32 + tm * 16 + r * 8 + q;
                int c = tn * 8 + id * 2;
                int j0 = c * 64 + m;
                uint32_t hw, lw;
                split2(kern[o * 2048 + j0], kern[o * 2048 + j0 + 64], hw, lw);
                g_kh[o * 1024 + W] = hw;
                g_kl[o * 1024 + W] = lw;
            }
        }
        return;
    }

    const int pos0 = blockIdx.x * 2;
    const int b = pos0 >> 9;

    if (blockIdx.x < 512) out[blockIdx.x * 256 + t] = 0.f;   // phase B accumulates

    float iv[2]; int ibase[2];
    #pragma unroll
    for (int s = 0; s < 2; ++s) { iv[s] = idxg[pos0 + s]; ibase[s] = (int)floorf(iv[s]); }

    // ---------- load windows, split to bf16 hi/lo, store [k][c] pitch-80 ----------
    #pragma unroll
    for (int i = 0; i < 4; ++i) {
        int u  = t + i * 256;               // 0..1023
        int p  = u >> 9;
        int s2 = u & 511;
        int k  = s2 >> 3, c4 = s2 & 7;
        int t1 = ibase[p] + k - 32;
        float4 v = make_float4(0.f, 0.f, 0.f, 0.f);
        if (t1 >= 0 && t1 < NT1)
            v = reinterpret_cast<const float4*>(x)[(b * NT1 + t1) * 8 + c4];
        uint32_t hw0, lw0, hw1, lw1;
        split2(v.x, v.y, hw0, lw0);
        split2(v.z, v.w, hw1, lw1);
        char* base = sm + SA_X + p * 10240 + k * 80 + c4 * 8;
        reinterpret_cast<uint32_t*>(base)[0] = hw0;
        reinterpret_cast<uint32_t*>(base)[1] = hw1;
        reinterpret_cast<uint32_t*>(base + 5120)[0] = lw0;
        reinterpret_cast<uint32_t*>(base + 5120)[1] = lw1;
    }
    // ---------- taps (Dirichlet), bf16 hi/lo ----------
    if (t < 128) {
        int p = t >> 6, j = t & 63;
        float f  = iv[p] - floorf(iv[p]);
        float u  = f + (float)j;
        float a  = u * 0.098174770424681038f;   // pi/32
        float s2 = sinf(0.5f * a);
        float wv;
        if (fabsf(s2) < 1e-5f) wv = 1.f;
        else wv = (1.f + 2.f * sinf(15.5f * a) * cosf(16.f * a) / s2 + cosf(32.f * a)) * (1.f / 64.f);
        __nv_bfloat16 hv = __float2bfloat16_rn(wv);
        __nv_bfloat16 lv = __float2bfloat16_rn(wv - __bfloat162float(hv));
        reinterpret_cast<uint16_t*>(sm + SA_TR + p * 256)[j]       = *reinterpret_cast<uint16_t*>(&hv);
        reinterpret_cast<uint16_t*>(sm + SA_TR + p * 256 + 128)[j] = *reinterpret_cast<uint16_t*>(&lv);
    }
    __syncthreads();

    // ---------- odd-offset packed tap tables ----------
    if (t < 64) {
        int p = t >> 5, w = t & 31;
        const uint16_t* rh = reinterpret_cast<const uint16_t*>(sm + SA_TR + p * 256);
        const uint16_t* rl = rh + 64;
        uint32_t ph = (uint32_t)rh[2 * w + 1] | ((uint32_t)rh[(2 * w + 2) & 63] << 16);
        uint32_t pl = (uint32_t)rl[2 * w + 1] | ((uint32_t)rl[(2 * w + 2) & 63] << 16);
        reinterpret_cast<uint32_t*>(sm + SA_TP + p * 256)[w]       = ph;
        reinterpret_cast<uint32_t*>(sm + SA_TP + p * 256 + 128)[w] = pl;
    }
    __syncthreads();

    const int p  = wid >> 2;                // warp position
    const int mh = (wid >> 1) & 1;          // m half (32 rows)
    const int ch = wid & 1;                 // c half (16 cols)

    // ---------- build W rows m = mh*32 + ch*16 .. +15 ----------
    {
        const uint32_t* rawH = reinterpret_cast<const uint32_t*>(sm + SA_TR + p * 256);
        const uint32_t* rawL = reinterpret_cast<const uint32_t*>(sm + SA_TR + p * 256 + 128);
        const uint32_t* p1H  = reinterpret_cast<const uint32_t*>(sm + SA_TP + p * 256);
        const uint32_t* p1L  = reinterpret_cast<const uint32_t*>(sm + SA_TP + p * 256 + 128);
        char* wtH = sm + SA_W + p * 16384;
        char* wtL = wtH + 8192;
        #pragma unroll 4
        for (int rr = 0; rr < 16; ++rr) {
            int m = mh * 32 + ch * 16 + rr;
            uint32_t wh, wl;
            if (m & 1) {
                int u = (lane - ((m + 1) >> 1)) & 31;
                wh = p1H[u]; wl = p1L[u];
            } else {
                int u = (lane - (m >> 1)) & 31;
                wh = rawH[u]; wl = rawL[u];
            }
            uint32_t off = (uint32_t)m * 128u + (uint32_t)(((lane >> 2) ^ (m & 7)) << 4)
                         + (uint32_t)((lane & 3) << 2);
            *reinterpret_cast<uint32_t*>(wtH + off) = wh;
            *reinterpret_cast<uint32_t*>(wtL + off) = wl;
        }
    }
    __syncthreads();

    // ---------- MMA: warp computes xs rows mh*32..+31, cols ch*16..+15 ----------
    const uint32_t sb = smem_u32(sm);
    const uint32_t aHb = sb + SA_W + p * 16384;
    const uint32_t aLb = aHb + 8192;
    const uint32_t xHb = sb + SA_X + p * 10240;
    const uint32_t xLb = xHb + 5120;
    const int arow0 = mh * 32 + (lane & 15);
    const int aKU   = lane >> 4;
    const int bg = lane >> 3, bi = lane & 7;
    const int bkOff = (bg & 1) * 8 + bi;
    const int bnCol = ch * 16 + (bg >> 1) * 8;

    float acc[2][2][4];
    #pragma unroll
    for (int tm = 0; tm < 2; ++tm)
        #pragma unroll
        for (int tn = 0; tn < 2; ++tn)
            #pragma unroll
            for (int q = 0; q < 4; ++q) acc[tm][tn][q] = 0.f;

    #pragma unroll
    for (int s = 0; s < 4; ++s) {
        uint32_t ah[2][4], al[2][4];
        #pragma unroll
        for (int tm = 0; tm < 2; ++tm) {
            int ar = arow0 + tm * 16;
            uint32_t sw = (uint32_t)(((2 * s + aKU) ^ (ar & 7)) << 4);
            ldm4(ah[tm], aHb + (uint32_t)ar * 128u + sw);
            ldm4(al[tm], aLb + (uint32_t)ar * 128u + sw);
        }
        uint32_t bh[4], bl[4];
        uint32_t baddr = (uint32_t)(s * 16 + bkOff) * 80u + (uint32_t)bnCol * 2u;
        ldm4t(bh, xHb + baddr);
        ldm4t(bl, xLb + baddr);
        #pragma unroll
        for (int tm = 0; tm < 2; ++tm)
            #pragma unroll
            for (int tn = 0; tn < 2; ++tn) {
                mma_bf16(acc[tm][tn], ah[tm], bh[2 * tn], bh[2 * tn + 1]);
                mma_bf16(acc[tm][tn], al[tm], bh[2 * tn], bh[2 * tn + 1]);
                mma_bf16(acc[tm][tn], ah[tm], bl[2 * tn], bl[2 * tn + 1]);
            }
    }

    // ---------- epilogue: sigma-order store (coalesced) ----------
    uint32_t* oh = g_xh + (pos0 + p) * 1024 + mh * 512;
    uint32_t* ol = g_xl + (pos0 + p) * 1024 + mh * 512;
    #pragma unroll
    for (int tm = 0; tm < 2; ++tm)
        #pragma unroll
        for (int tn = 0; tn < 2; ++tn) {
            int T = tm * 4 + ch * 2 + tn;
            #pragma unroll
            for (int r = 0; r < 2; ++r) {
                uint32_t hw, lw;
                split2(acc[tm][tn][2 * r], acc[tm][tn][2 * r + 1], hw, lw);
                oh[T * 64 + r * 32 + lane] = hw;
                ol[T * 64 + r * 32 + lane] = lw;
            }
        }
}

// ---------------- Phase B: out += xs @ kernel^T (sigma order), cp.async pipeline ----------------
// chunk = 32 words (64 bf16). buffer: A hi 8K, A lo 8K, B hi 8K, B lo 8K = 32K; x2 = 64K.
#define SB_TOT 65536

__global__ __launch_bounds__(256, 3)
void cc1d_phaseB(const float* __restrict__ bias, float* __restrict__ out) {
    extern __shared__ char sm[];
    const uint32_t sb = smem_u32(sm);
    const int t = threadIdx.x, wid = t >> 5, lane = t & 31;
    const int mt = blockIdx.x >> 3;
    const int ks = blockIdx.x & 7;
    const int p0 = mt * 64;

    const int mtile = wid >> 1;
    const int nh    = wid & 1;
    const int arow  = mtile * 16 + (lane & 15);
    const int aKU   = lane >> 4;
    const int nIdx  = (lane & 7) + ((lane >> 4) << 3);
    const int bKU   = (lane >> 3) & 1;

    // staging map (8 cp.async of 16B per thread per chunk)
    const uint32_t* gsrc[4] = {g_xh, g_xl, g_kh, g_kl};

    #define STAGE(CH, BUF) do {                                                    \
        int wb0_ = ks * 128 + (CH) * 32;                                           \
        uint32_t bbase_ = (uint32_t)(BUF) * 32768u;                                \
        _Pragma("unroll")                                                          \
        for (int i_ = 0; i_ < 8; ++i_) {                                           \
            int u_   = t + i_ * 256;                                               \
            int arr_ = u_ >> 9;                                                    \
            int rem_ = u_ & 511;                                                   \
            int row_ = rem_ >> 3;                                                  \
            int un_  = rem_ & 7;                                                   \
            int srow_ = (arr_ < 2) ? (p0 + row_) : row_;                           \
            const uint32_t* sp_ = gsrc[arr_] + (size_t)srow_ * 1024 + wb0_ + un_ * 4; \
            uint32_t d_ = sb + bbase_ + (uint32_t)arr_ * 8192u                     \
                        + (uint32_t)row_ * 128u + (uint32_t)((un_ ^ (row_ & 7)) << 4); \
            cpasync16(d_, sp_);                                                    \
        }                                                                          \
    } while (0)

    float acc[4][4];
    #pragma unroll
    for (int tn = 0; tn < 4; ++tn)
        #pragma unroll
        for (int q = 0; q < 4; ++q) acc[tn][q] = 0.f;

    STAGE(0, 0);
    asm volatile("cp.async.commit_group;" ::: "memory");
    STAGE(1, 1);
    asm volatile("cp.async.commit_group;" ::: "memory");

    #pragma unroll
    for (int c = 0; c < 4; ++c) {
        if (c < 3) asm volatile("cp.async.wait_group 1;" ::: "memory");
        else       asm volatile("cp.async.wait_group 0;" ::: "memory");
        __syncthreads();

        const uint32_t bbase = sb + (uint32_t)(c & 1) * 32768u;
        #pragma unroll
        for (int s = 0; s < 4; ++s) {
            uint32_t ah[4], al[4];
            {
                uint32_t sw = (uint32_t)(((2 * s + aKU) ^ (arow & 7)) << 4);
                ldm4(ah, bbase + (uint32_t)arow * 128u + sw);
                ldm4(al, bbase + 8192u + (uint32_t)arow * 128u + sw);
            }
            uint32_t bh[2][4], bl[2][4];
            #pragma unroll
            for (int g = 0; g < 2; ++g) {
                int nr = nh * 32 + g * 16 + nIdx;
                uint32_t sw = (uint32_t)(((2 * s + bKU) ^ (nr & 7)) << 4);
                ldm4(bh[g], bbase + 16384u + (uint32_t)nr * 128u + sw);
                ldm4(bl[g], bbase + 24576u + (uint32_t)nr * 128u + sw);
            }
            #pragma unroll
            for (int tn = 0; tn < 4; ++tn) {
                int g = tn >> 1, q0 = (tn & 1) * 2;
                mma_bf16(acc[tn], ah, bh[g][q0], bh[g][q0 + 1]);
                mma_bf16(acc[tn], al, bh[g][q0], bh[g][q0 + 1]);
                mma_bf16(acc[tn], ah, bl[g][q0], bl[g][q0 + 1]);
            }
        }
        __syncthreads();
        if (c + 2 < 4) {
            STAGE(c + 2, c & 1);
            asm volatile("cp.async.commit_group;" ::: "memory");
        }
    }

    // ---------- epilogue: atomic accumulate, bias folded on split 0 ----------
    const int quad = lane >> 2, id = lane & 3;
    const int r0 = p0 + mtile * 16 + quad;
    #pragma unroll
    for (int tn = 0; tn < 4; ++tn) {
        int c0 = nh * 32 + tn * 8 + id * 2;
        float b0 = 0.f, b1 = 0.f;
        if (ks == 0) { b0 = bias[c0]; b1 = bias[c0 + 1]; }
        atomicAdd(&out[r0 * NOC + c0],           acc[tn][0] + b0);
        atomicAdd(&out[r0 * NOC + c0 + 1],       acc[tn][1] + b1);
        atomicAdd(&out[(r0 + 8) * NOC + c0],     acc[tn][2] + b0);
        atomicAdd(&out[(r0 + 8) * NOC + c0 + 1], acc[tn][3] + b1);
    }
    #undef STAGE
}

extern "C" void kernel_launch(void* const* d_in, const int* in_sizes, int n_in,
                              void* d_out, int out_size)
{
    const float* x    = (const float*)d_in[0];
    const float* idx  = (const float*)d_in[1];
    const float* kern = (const float*)d_in[2];
    const float* bias = (const float*)d_in[3];
    float* out = (float*)d_out;
    (void)in_sizes; (void)n_in; (void)out_size;

    cudaFuncSetAttribute(cc1d_phaseA, cudaFuncAttributeMaxDynamicSharedMemorySize, SA_TOT);
    cc1d_phaseA<<<1024 + 32, 256, SA_TOT>>>(x, idx, kern, out);

    cudaFuncSetAttribute(cc1d_phaseB, cudaFuncAttributeMaxDynamicSharedMemorySize, SB_TOT);
    cc1d_phaseB<<<32 * 8, 256, SB_TOT>>>(bias, out);
}